// round 6
// baseline (speedup 1.0000x reference)
#include <cuda_runtime.h>
#include <cuda_bf16.h>
#include <math.h>

// Soft joint histogram: out[b,k,j] = (1/N) * sum_n phi_k(x[b,n]) * phi_j(y[b,n])
// phi = difference of sigmoids, width W = L/2.5. Stencil = diamond |di|+|dj| <= 5
// (57 taps). Split: 37 hot taps -> smem ATOMS (SM atomic pipe), 20 cold taps ->
// red.global.add.f32 into an L2-resident padded accumulator (L2 atomic pipe).

#define KBINS     256
#define RAD       4
#define WIN       9
#define NEDGE     10
#define SLAB_ROWS 128
#define NSLABS    2
#define NCHUNK    9            // grid = 8*2*9 = 144 blocks (one wave)
#define PROWS     144
#define PITCH     264          // smem col pitch
#define GDIM      264          // padded global accumulator dim (256 + 4 each side)
#define NPIX      65536
#define BMAX      8
#define CHUNK_PX  7282
#define NTHREADS  512

// Workspace: one 128x256 partial per block. 144 * 32768 floats = 18.9 MB.
__device__ float g_ws[BMAX * NSLABS * NCHUNK * SLAB_ROWS * KBINS];
// L2-resident accumulator for the 20 outer taps: 8 * 264 * 264 floats = 2.2 MB.
__device__ float g_acc[BMAX * GDIM * GDIM];

__global__ void zero_acc_kernel(int total4) {
    int i = blockIdx.x * blockDim.x + threadIdx.x;
    if (i < total4) ((float4*)g_acc)[i] = make_float4(0.f, 0.f, 0.f, 0.f);
}

// phi for the 9 bins around value t (= x*256), k0 = floor bin.
// One __expf + one rcp.approx via prefix/suffix products of A_m = 1 + E0*R^m.
__device__ __forceinline__ void compute_phis(float t, int k0, float* __restrict__ phi) {
    const float R = 12.182493960703473f;   // exp(2.5)
    float z0 = (t - (float)(k0 - RAD)) * 2.5f;   // in [10, 12.5)
    float E = __expf(-z0);

    float A[NEDGE];
    float Ei = E;
#pragma unroll
    for (int m = 0; m < NEDGE; m++) { A[m] = 1.0f + Ei; Ei *= R; }

    float pre[NEDGE], suf[NEDGE];
    pre[0] = A[0];
#pragma unroll
    for (int m = 1; m < NEDGE; m++) pre[m] = pre[m - 1] * A[m];
    suf[NEDGE - 1] = A[NEDGE - 1];
#pragma unroll
    for (int m = NEDGE - 2; m >= 0; m--) suf[m] = suf[m + 1] * A[m];

    float inv;
    asm("rcp.approx.f32 %0, %1;" : "=f"(inv) : "f"(pre[NEDGE - 1]));

    float s[NEDGE];
    s[0] = suf[1] * inv;
#pragma unroll
    for (int m = 1; m < NEDGE - 1; m++) s[m] = pre[m - 1] * suf[m + 1] * inv;
    s[NEDGE - 1] = pre[NEDGE - 2] * inv;

#pragma unroll
    for (int i = 0; i < WIN; i++) phi[i] = s[i] - s[i + 1];
}

__global__ void __launch_bounds__(NTHREADS, 1)
hist_kernel(const float* __restrict__ x, const float* __restrict__ y) {
    extern __shared__ float sh[];
    const int c    = blockIdx.x;
    const int slab = blockIdx.y;
    const int b    = blockIdx.z;
    const int slab_lo = slab * SLAB_ROWS;

    for (int i = threadIdx.x; i < PROWS * PITCH; i += NTHREADS) sh[i] = 0.0f;
    __syncthreads();

    const int start = c * CHUNK_PX;
    const int end   = min(start + CHUNK_PX, NPIX);
    const float* __restrict__ xb = x + b * NPIX;
    const float* __restrict__ yb = y + b * NPIX;
    float* __restrict__ accb = &g_acc[b * GDIM * GDIM];

    for (int p = start + threadIdx.x; p < end; p += NTHREADS) {
        float tx = xb[p] * 256.0f;
        int kx = (int)tx;
        if (kx < slab_lo - RAD || kx > slab_lo + SLAB_ROWS - 1 + RAD) continue;

        float ty = yb[p] * 256.0f;
        int ky = (int)ty;

        float phi1[WIN], phi2[WIN];
        compute_phis(tx, kx, phi1);
        compute_phis(ty, ky, phi2);

        // smem: row_mem = (kx - slab_lo + 4) + ii, col_mem = ky + jj (padded)
        float* sbase = &sh[(kx - slab_lo + 4) * PITCH + ky];
        // global acc: row kx+ii-4+4 = kx+ii, col ky+jj-4+4 = ky+jj (padded)
        float* gbase = &accb[kx * GDIM + ky];

        // 37 hot taps -> smem atomics
#pragma unroll
        for (int ii = 0; ii < WIN; ii++) {
            float p1 = phi1[ii];
#pragma unroll
            for (int jj = 0; jj < WIN; jj++) {
                const int di = (ii < 4) ? (4 - ii) : (ii - 4);
                const int dj = (jj < 4) ? (4 - jj) : (jj - 4);
                if (di + dj > 5) continue;                       // outside diamond
                if (dj >= 3 || (dj == 2 && di == 3)) continue;   // routed to L2
                atomicAdd(&sbase[ii * PITCH + jj], p1 * phi2[jj]);
            }
        }

        // 20 cold taps -> L2 REDG (only the slab that owns kx, to avoid dup)
        if (kx >= slab_lo && kx < slab_lo + SLAB_ROWS) {
#pragma unroll
            for (int ii = 0; ii < WIN; ii++) {
                float p1 = phi1[ii];
#pragma unroll
                for (int jj = 0; jj < WIN; jj++) {
                    const int di = (ii < 4) ? (4 - ii) : (ii - 4);
                    const int dj = (jj < 4) ? (4 - jj) : (jj - 4);
                    if (di + dj > 5) continue;
                    if (!(dj >= 3 || (dj == 2 && di == 3))) continue;
                    atomicAdd(&gbase[ii * GDIM + jj], p1 * phi2[jj]);  // -> REDG
                }
            }
        }
    }
    __syncthreads();

    // flush real 128x256 region (rows 8..135, cols 4..259) -> workspace
    float4* __restrict__ dst =
        (float4*)&g_ws[(size_t)(((b * NSLABS) + slab) * NCHUNK + c) * (SLAB_ROWS * KBINS)];
    for (int i = threadIdx.x; i < SLAB_ROWS * KBINS / 4; i += NTHREADS) {
        int row = i >> 6;          // 64 float4 per 256-col row
        int c4  = i & 63;
        const float4* src = (const float4*)&sh[(row + 8) * PITCH + 4];
        dst[i] = src[c4];
    }
}

__global__ void __launch_bounds__(256)
reduce_kernel(float* __restrict__ out, int total4) {
    int idx = blockIdx.x * blockDim.x + threadIdx.x;   // float4 index
    if (idx >= total4) return;
    int k = (idx >> 6) & 255;
    int b = idx >> 14;
    int slab = k >> 7;
    int rowj4 = ((k & 127) << 6) | (idx & 63);
    const float4* __restrict__ base = (const float4*)
        &g_ws[(size_t)((b * NSLABS + slab) * NCHUNK) * (SLAB_ROWS * KBINS)];

    float4 v[10];
#pragma unroll
    for (int cc = 0; cc < NCHUNK; cc++)
        v[cc] = base[(size_t)cc * (SLAB_ROWS * KBINS / 4) + rowj4];
    // L2-accumulator contribution: row k+4, col (j0+4), j0 = (idx&63)*4
    int j0 = (idx & 63) << 2;
    v[9] = *(const float4*)&g_acc[b * GDIM * GDIM + (k + 4) * GDIM + (j0 + 4)];

    float4 s = make_float4(0.f, 0.f, 0.f, 0.f);
#pragma unroll
    for (int cc = 0; cc < 10; cc++) {
        s.x += v[cc].x; s.y += v[cc].y; s.z += v[cc].z; s.w += v[cc].w;
    }
    const float inv = 1.0f / (float)NPIX;
    s.x *= inv; s.y *= inv; s.z *= inv; s.w *= inv;
    ((float4*)out)[idx] = s;
}

extern "C" void kernel_launch(void* const* d_in, const int* in_sizes, int n_in,
                              void* d_out, int out_size) {
    const float* x = (const float*)d_in[0];
    const float* y = (const float*)d_in[1];
    float* out = (float*)d_out;

    int B = in_sizes[0] / NPIX;

    int acc4 = BMAX * GDIM * GDIM / 4;           // 139392 float4
    zero_acc_kernel<<<(acc4 + 255) / 256, 256>>>(acc4);

    size_t smem = (size_t)PROWS * PITCH * sizeof(float);  // 152 KB
    cudaFuncSetAttribute(hist_kernel, cudaFuncAttributeMaxDynamicSharedMemorySize, (int)smem);

    dim3 grid(NCHUNK, NSLABS, B);
    hist_kernel<<<grid, NTHREADS, smem>>>(x, y);

    int total4 = B * KBINS * KBINS / 4;
    reduce_kernel<<<(total4 + 255) / 256, 256>>>(out, total4);
}

// round 7
// speedup vs baseline: 1.0619x; 1.0619x over previous
#include <cuda_runtime.h>
#include <cuda_fp16.h>
#include <cuda_bf16.h>
#include <math.h>

// Soft joint histogram: out[b,k,j] = (1/N) * sum_n phi_k(x[b,n]) * phi_j(y[b,n])
// Diamond stencil |di|+|dj| <= 5 (57 taps). Split:
//   5 "plus" taps (|di|+|dj|<=1, ~92% of mass) -> fp32 smem atomics
//   52 outer taps -> f16x2 packed smem atomics (red.shared.add.noftz.f16x2)
// Parity handled by two phase-shifted f16 grids (A: cols (2p,2p+1), B: (2p+1,2p+2))
// so every span is exactly pair-aligned: 30 f16x2 words + 5 f32 = 35 atomic lanes/px.

#define KBINS     256
#define RAD       4
#define WIN       9
#define NEDGE     10
#define SLAB_ROWS 88
#define NSLABS    3
#define NCHUNK    6            // grid = 8*3*6 = 144 blocks (one wave)
#define NPIX      65536
#define BMAX      8
#define CHUNK_PX  10923        // ceil(65536/6)
#define NTHREADS  512

// fp32 grid: rows (88 + 5 pad below + 5 above) x pitch 260 (256 + 1 pad each side)
#define F32ROWS   98
#define F32PITCH  260
#define OFF_F32   0
#define F32SIZE   (F32ROWS * F32PITCH)        // 25480 floats
// f16 grids: rows (88 + 8 pad below + 8 above) x 136 pairs
#define F16ROWS   104
#define PAIRS     136
#define F16SIZE   (F16ROWS * PAIRS)           // 14144 words (as float-sized slots)
#define OFF_A     F32SIZE                     // 25480
#define OFF_B     (F32SIZE + F16SIZE)         // 39624
#define TOT_F     (F32SIZE + 2 * F16SIZE)     // 53768 floats = 215072 B

#define SLABK     (SLAB_ROWS * KBINS)         // 22528

// Workspace: one 88x256 partial per block. 144 * 22528 floats = 13.0 MB.
__device__ float g_ws[BMAX * NSLABS * NCHUNK * SLABK];

// phi for the 9 bins around value t (= x*256), k0 = floor bin.
// One __expf + one rcp.approx via prefix/suffix products of A_m = 1 + E0*R^m.
__device__ __forceinline__ void compute_phis(float t, int k0, float* __restrict__ phi) {
    const float R = 12.182493960703473f;   // exp(2.5)
    float z0 = (t - (float)(k0 - RAD)) * 2.5f;   // in [10, 12.5)
    float E = __expf(-z0);

    float A[NEDGE];
    float Ei = E;
#pragma unroll
    for (int m = 0; m < NEDGE; m++) { A[m] = 1.0f + Ei; Ei *= R; }

    float pre[NEDGE], suf[NEDGE];
    pre[0] = A[0];
#pragma unroll
    for (int m = 1; m < NEDGE; m++) pre[m] = pre[m - 1] * A[m];
    suf[NEDGE - 1] = A[NEDGE - 1];
#pragma unroll
    for (int m = NEDGE - 2; m >= 0; m--) suf[m] = suf[m + 1] * A[m];

    float inv;
    asm("rcp.approx.f32 %0, %1;" : "=f"(inv) : "f"(pre[NEDGE - 1]));

    float s[NEDGE];
    s[0] = suf[1] * inv;
#pragma unroll
    for (int m = 1; m < NEDGE - 1; m++) s[m] = pre[m - 1] * suf[m + 1] * inv;
    s[NEDGE - 1] = pre[NEDGE - 2] * inv;

#pragma unroll
    for (int i = 0; i < WIN; i++) phi[i] = s[i] - s[i + 1];
}

// Packed f16x2 reduction into shared memory (no return value -> RED).
#define H2RED(addr, va, vb) do {                                             \
    __half2 _hh = __floats2half2_rn((va), (vb));                             \
    unsigned int _u = *(unsigned int*)&_hh;                                  \
    asm volatile("red.shared.add.noftz.f16x2 [%0], %1;"                      \
                 :: "r"(addr), "r"(_u) : "memory");                          \
} while (0)

__device__ __forceinline__ unsigned int span_addr(unsigned int rA, unsigned int rB, int c0) {
    unsigned int base = (c0 & 1) ? rB : rA;
    return base + (unsigned int)((c0 >> 1) << 2);
}

__global__ void __launch_bounds__(NTHREADS, 1)
hist_kernel(const float* __restrict__ x, const float* __restrict__ y) {
    extern __shared__ float sh[];
    const int c    = blockIdx.x;
    const int slab = blockIdx.y;
    const int b    = blockIdx.z;
    const int slab_lo = slab * SLAB_ROWS;

    // zero all three grids
    {
        float4* sh4 = (float4*)sh;
        for (int i = threadIdx.x; i < TOT_F / 4; i += NTHREADS)
            sh4[i] = make_float4(0.f, 0.f, 0.f, 0.f);
    }
    __syncthreads();

    const unsigned int sb = (unsigned int)__cvta_generic_to_shared(sh);
    const unsigned int aBase = sb + OFF_A * 4u;
    const unsigned int bBase = sb + OFF_B * 4u;

    const int start = c * CHUNK_PX;
    const int end   = min(start + CHUNK_PX, NPIX);
    const float* __restrict__ xb = x + b * NPIX;
    const float* __restrict__ yb = y + b * NPIX;

    for (int p = start + threadIdx.x; p < end; p += NTHREADS) {
        float tx = xb[p] * 256.0f;
        int kx = (int)tx;
        int kxr = kx - slab_lo;
        // window rows [kx-4, kx+4] intersect [0, 88) <=> kxr in [-4, 91]
        if ((unsigned)(kxr + 4) > 95u) continue;

        float ty = yb[p] * 256.0f;
        int ky = (int)ty;

        float P1[WIN], P[WIN];
        compute_phis(tx, kx, P1);
        compute_phis(ty, ky, P);

        // ---- 5 fp32 "plus" taps ----
        float* f0 = &sh[(kxr + 5) * F32PITCH + (ky + 1)];
        atomicAdd(f0 - F32PITCH, P1[3] * P[4]);
        atomicAdd(f0 - 1,        P1[4] * P[3]);
        atomicAdd(f0,            P1[4] * P[4]);
        atomicAdd(f0 + 1,        P1[4] * P[5]);
        atomicAdd(f0 + F32PITCH, P1[5] * P[4]);

        // ---- 52 outer taps as 30 f16x2 words ----
        unsigned int rA = aBase + (unsigned int)(kxr + 4) * (PAIRS * 4u);
        unsigned int rB = bBase + (unsigned int)(kxr + 4) * (PAIRS * 4u);

        { // ii=0 (di=4): jj in [3,5]
            float q = P1[0];
            unsigned int s = span_addr(rA, rB, ky + 3);
            H2RED(s,     q * P[3], q * P[4]);
            H2RED(s + 4, q * P[5], 0.0f);
        }
        rA += PAIRS * 4u; rB += PAIRS * 4u;
        { // ii=1 (di=3): jj in [2,6]
            float q = P1[1];
            unsigned int s = span_addr(rA, rB, ky + 2);
            H2RED(s,     q * P[2], q * P[3]);
            H2RED(s + 4, q * P[4], q * P[5]);
            H2RED(s + 8, q * P[6], 0.0f);
        }
        rA += PAIRS * 4u; rB += PAIRS * 4u;
        { // ii=2 (di=2): jj in [1,7]
            float q = P1[2];
            unsigned int s = span_addr(rA, rB, ky + 1);
            H2RED(s,      q * P[1], q * P[2]);
            H2RED(s + 4,  q * P[3], q * P[4]);
            H2RED(s + 8,  q * P[5], q * P[6]);
            H2RED(s + 12, q * P[7], 0.0f);
        }
        rA += PAIRS * 4u; rB += PAIRS * 4u;
        { // ii=3 (di=1): jj in [0,3] u [5,8]  (jj=4 is fp32)
            float q = P1[3];
            unsigned int s1 = span_addr(rA, rB, ky);
            H2RED(s1,     q * P[0], q * P[1]);
            H2RED(s1 + 4, q * P[2], q * P[3]);
            unsigned int s2 = span_addr(rA, rB, ky + 5);
            H2RED(s2,     q * P[5], q * P[6]);
            H2RED(s2 + 4, q * P[7], q * P[8]);
        }
        rA += PAIRS * 4u; rB += PAIRS * 4u;
        { // ii=4 (di=0): jj in [0,2] u [6,8]  (jj=3,4,5 are fp32)
            float q = P1[4];
            unsigned int s1 = span_addr(rA, rB, ky);
            H2RED(s1,     q * P[0], q * P[1]);
            H2RED(s1 + 4, q * P[2], 0.0f);
            unsigned int s2 = span_addr(rA, rB, ky + 6);
            H2RED(s2,     q * P[6], q * P[7]);
            H2RED(s2 + 4, q * P[8], 0.0f);
        }
        rA += PAIRS * 4u; rB += PAIRS * 4u;
        { // ii=5 (di=1)
            float q = P1[5];
            unsigned int s1 = span_addr(rA, rB, ky);
            H2RED(s1,     q * P[0], q * P[1]);
            H2RED(s1 + 4, q * P[2], q * P[3]);
            unsigned int s2 = span_addr(rA, rB, ky + 5);
            H2RED(s2,     q * P[5], q * P[6]);
            H2RED(s2 + 4, q * P[7], q * P[8]);
        }
        rA += PAIRS * 4u; rB += PAIRS * 4u;
        { // ii=6 (di=2)
            float q = P1[6];
            unsigned int s = span_addr(rA, rB, ky + 1);
            H2RED(s,      q * P[1], q * P[2]);
            H2RED(s + 4,  q * P[3], q * P[4]);
            H2RED(s + 8,  q * P[5], q * P[6]);
            H2RED(s + 12, q * P[7], 0.0f);
        }
        rA += PAIRS * 4u; rB += PAIRS * 4u;
        { // ii=7 (di=3)
            float q = P1[7];
            unsigned int s = span_addr(rA, rB, ky + 2);
            H2RED(s,     q * P[2], q * P[3]);
            H2RED(s + 4, q * P[4], q * P[5]);
            H2RED(s + 8, q * P[6], 0.0f);
        }
        rA += PAIRS * 4u; rB += PAIRS * 4u;
        { // ii=8 (di=4)
            float q = P1[8];
            unsigned int s = span_addr(rA, rB, ky + 3);
            H2RED(s,     q * P[3], q * P[4]);
            H2RED(s + 4, q * P[5], 0.0f);
        }
    }
    __syncthreads();

    // flush: combine f32 + A + B -> workspace partial (88x256)
    float* __restrict__ ws =
        &g_ws[(size_t)((b * NSLABS + slab) * NCHUNK + c) * SLABK];
    const unsigned int* A32 = (const unsigned int*)&sh[OFF_A];
    const unsigned int* B32 = (const unsigned int*)&sh[OFF_B];
    for (int i = threadIdx.x; i < SLABK; i += NTHREADS) {
        int R = i >> 8;
        int C = i & 255;
        float v = sh[(R + 5) * F32PITCH + (C + 1)];
        int cm = C + 4;
        unsigned int aw = A32[(R + 8) * PAIRS + (cm >> 1)];
        unsigned int bw = B32[(R + 8) * PAIRS + ((cm - 1) >> 1)];
        unsigned short ah = (cm & 1) ? (unsigned short)(aw >> 16) : (unsigned short)(aw & 0xffff);
        unsigned short bh = (cm & 1) ? (unsigned short)(bw & 0xffff) : (unsigned short)(bw >> 16);
        v += __half2float(__ushort_as_half(ah)) + __half2float(__ushort_as_half(bh));
        ws[i] = v;
    }
}

__global__ void __launch_bounds__(256)
reduce_kernel(float* __restrict__ out, int total4) {
    int idx = blockIdx.x * blockDim.x + threadIdx.x;   // float4 index
    if (idx >= total4) return;
    int k = (idx >> 6) & 255;
    int b = idx >> 14;
    int slab = k / SLAB_ROWS;
    int row  = k - slab * SLAB_ROWS;
    int j4   = idx & 63;
    const float4* __restrict__ base = (const float4*)
        &g_ws[(size_t)((b * NSLABS + slab) * NCHUNK) * SLABK];
    size_t off = (size_t)row * (KBINS / 4) + j4;

    float4 s = make_float4(0.f, 0.f, 0.f, 0.f);
#pragma unroll
    for (int cc = 0; cc < NCHUNK; cc++) {
        float4 v = base[(size_t)cc * (SLABK / 4) + off];
        s.x += v.x; s.y += v.y; s.z += v.z; s.w += v.w;
    }
    const float inv = 1.0f / (float)NPIX;
    s.x *= inv; s.y *= inv; s.z *= inv; s.w *= inv;
    ((float4*)out)[idx] = s;
}

extern "C" void kernel_launch(void* const* d_in, const int* in_sizes, int n_in,
                              void* d_out, int out_size) {
    const float* x = (const float*)d_in[0];
    const float* y = (const float*)d_in[1];
    float* out = (float*)d_out;

    int B = in_sizes[0] / NPIX;

    size_t smem = (size_t)TOT_F * sizeof(float);   // 215072 B
    cudaFuncSetAttribute(hist_kernel, cudaFuncAttributeMaxDynamicSharedMemorySize, (int)smem);

    dim3 grid(NCHUNK, NSLABS, B);
    hist_kernel<<<grid, NTHREADS, smem>>>(x, y);

    int total4 = B * KBINS * KBINS / 4;
    reduce_kernel<<<(total4 + 255) / 256, 256>>>(out, total4);
}

// round 8
// speedup vs baseline: 1.1883x; 1.1191x over previous
#include <cuda_runtime.h>
#include <cuda_bf16.h>
#include <math.h>

// Soft joint histogram as a bucketed tile-GEMM.
// out[b,k,j] = (1/N) sum_n phi_k(x_n) phi_j(y_n); phi has a 9-bin window.
// Bins tiled 16x16 -> pixel belongs to <=4 (row-tile, col-tile) buckets.
// Phase 1: scatter (x,y) into per-(b,a,c,subslot) bucket arrays (smem counters).
// Phase 2: per-bucket CTA computes the 16x16 output tile by register-blocked
//          FFMA outer products over staged phi rows. No atomics in hot path.

#define KBINS   256
#define RAD     4
#define WIN     9
#define NEDGE   10
#define NPIX    65536
#define BMAX    8
#define TILE    16
#define NT      16          // tiles per dim
#define NSUB    16          // sub-slots per bucket (one per phase-1 block)
#define CAP     80          // entries per (bucket, sub-slot); mean 36, +7.3 sigma
#define CHUNK   (NPIX / NSUB)   // 4096 pixels per phase-1 block
#define P1_THREADS 512
#define P2_THREADS 128
#define ENT_MAX (NSUB * CAP)    // 1280

// bucket id: bid = (b*256 + a*16 + c); slot base = (bid*NSUB + s)*CAP
__device__ float2 g_buck[BMAX * 256 * NSUB * CAP];   // ~21 MB
__device__ int    g_cnt [BMAX * 256 * NSUB];

// phi for 9 bins [k0-4, k0+4] around t = x*256. One __expf + one rcp.approx
// via prefix/suffix products of A_m = 1 + E0*R^m (edges are a geometric seq).
__device__ __forceinline__ void compute_phis(float t, int k0, float* __restrict__ phi) {
    const float R = 12.182493960703473f;   // exp(2.5)
    float z0 = (t - (float)(k0 - RAD)) * 2.5f;   // in [10, 12.5)
    float E = __expf(-z0);

    float A[NEDGE];
    float Ei = E;
#pragma unroll
    for (int m = 0; m < NEDGE; m++) { A[m] = 1.0f + Ei; Ei *= R; }

    float pre[NEDGE], suf[NEDGE];
    pre[0] = A[0];
#pragma unroll
    for (int m = 1; m < NEDGE; m++) pre[m] = pre[m - 1] * A[m];
    suf[NEDGE - 1] = A[NEDGE - 1];
#pragma unroll
    for (int m = NEDGE - 2; m >= 0; m--) suf[m] = suf[m + 1] * A[m];

    float inv;
    asm("rcp.approx.f32 %0, %1;" : "=f"(inv) : "f"(pre[NEDGE - 1]));

    float s[NEDGE];
    s[0] = suf[1] * inv;
#pragma unroll
    for (int m = 1; m < NEDGE - 1; m++) s[m] = pre[m - 1] * suf[m + 1] * inv;
    s[NEDGE - 1] = pre[NEDGE - 2] * inv;

#pragma unroll
    for (int i = 0; i < WIN; i++) phi[i] = s[i] - s[i + 1];
}

// ---------------- Phase 1: scatter pixels into buckets ----------------
__global__ void __launch_bounds__(P1_THREADS)
scatter_kernel(const float* __restrict__ x, const float* __restrict__ y) {
    __shared__ int cnt[256];
    const int s = blockIdx.x;      // sub-slot
    const int b = blockIdx.y;      // batch
    const int tid = threadIdx.x;

    for (int i = tid; i < 256; i += P1_THREADS) cnt[i] = 0;
    __syncthreads();

    const float* __restrict__ xb = x + b * NPIX;
    const float* __restrict__ yb = y + b * NPIX;
    const int p0 = s * CHUNK;

    for (int p = p0 + tid; p < p0 + CHUNK; p += P1_THREADS) {
        float xv = xb[p];
        float yv = yb[p];
        int kx = (int)(xv * 256.0f);
        int ky = (int)(yv * 256.0f);
        int alo = max(0, (kx - RAD) >> 4), ahi = min(NT - 1, (kx + RAD) >> 4);
        int clo = max(0, (ky - RAD) >> 4), chi = min(NT - 1, (ky + RAD) >> 4);
        for (int a = alo; a <= ahi; a++) {
            for (int c = clo; c <= chi; c++) {
                int lb = a * TILE + c;
                int slot = atomicAdd(&cnt[lb], 1);
                if (slot < CAP) {
                    size_t base = ((size_t)(b * 256 + lb) * NSUB + s) * CAP;
                    g_buck[base + slot] = make_float2(xv, yv);
                }
            }
        }
    }
    __syncthreads();
    for (int i = tid; i < 256; i += P1_THREADS)
        g_cnt[(b * 256 + i) * NSUB + s] = min(cnt[i], CAP);
}

// ---------------- Phase 2: per-bucket 16x16 tile GEMM ----------------
// axy row layout per staged entry: 32 floats = [phix 16 | phiy 16], 128B row,
// quad-level XOR swizzle: phys_quad = (logical_quad ^ (row & 7)).
__global__ void __launch_bounds__(P2_THREADS)
tile_kernel(float* __restrict__ out, int B) {
    __shared__ float2 ent[ENT_MAX];          // 10.25 KB
    __shared__ float  axy[128 * 32];         // 16 KB
    __shared__ float  red[256 * 8];          // 8 KB
    __shared__ int    cnts[NSUB];
    __shared__ int    pre[NSUB + 1];

    const int c = blockIdx.x, a = blockIdx.y, b = blockIdx.z;
    const int tid = threadIdx.x;
    const int bid = b * 256 + a * TILE + c;

    if (tid < NSUB) cnts[tid] = g_cnt[bid * NSUB + tid];
    __syncthreads();
    if (tid == 0) {
        int acc = 0;
#pragma unroll
        for (int s = 0; s < NSUB; s++) { pre[s] = acc; acc += cnts[s]; }
        pre[NSUB] = acc;
    }
    __syncthreads();

    // compact the 16 ragged sub-lists into contiguous smem
    for (int s = 0; s < NSUB; s++) {
        int n = cnts[s];
        const float2* __restrict__ src = &g_buck[((size_t)bid * NSUB + s) * CAP];
        for (int i = tid; i < n; i += P2_THREADS) ent[pre[s] + i] = src[i];
    }
    __syncthreads();

    const int total = pre[NSUB];
    const int g = tid >> 4;          // group 0..7 (entries e % 8 == g)
    const int t = tid & 15;          // cell-block within group
    const int i0 = (t >> 2) << 2;    // 4x4 cell block
    const int j0 = (t & 3) << 2;
    const int qa = t >> 2;           // phix quad 0..3
    const int qb = 4 + (t & 3);      // phiy quad 4..7

    float acc[16];
#pragma unroll
    for (int m = 0; m < 16; m++) acc[m] = 0.0f;

    const int klo = a * TILE;        // tile-local bin bases
    const int jlo = c * TILE;

    for (int base = 0; base < total; base += P2_THREADS) {
        // ---- stage up to 128 entries: compute phi, write swizzled rows ----
        {
            float* row = &axy[tid * 32];
            const int sw = tid & 7;
#pragma unroll
            for (int q = 0; q < 8; q++)
                *(float4*)&row[(q ^ sw) << 2] = make_float4(0.f, 0.f, 0.f, 0.f);
            int e = base + tid;
            if (e < total) {
                float2 v = ent[e];
                float tx = v.x * 256.0f;
                float ty = v.y * 256.0f;
                int kx = (int)tx, ky = (int)ty;
                float P1[WIN], P2[WIN];
                compute_phis(tx, kx, P1);
                compute_phis(ty, ky, P2);
                int bx = kx - RAD - klo;   // slot of P1[0] in [0,16) grid
                int by = ky - RAD - jlo;
#pragma unroll
                for (int u = 0; u < WIN; u++) {
                    int sl = bx + u;
                    if ((unsigned)sl < 16u)
                        row[(((sl >> 2) ^ sw) << 2) | (sl & 3)] = P1[u];
                }
#pragma unroll
                for (int u = 0; u < WIN; u++) {
                    int sl = by + u;
                    if ((unsigned)sl < 16u)
                        row[((((sl >> 2) + 4 ^ sw)) << 2) | (sl & 3)] = P2[u];
                }
            }
        }
        __syncthreads();
        // ---- accumulate: each group handles rows el = k*8 + g ----
#pragma unroll
        for (int k = 0; k < 16; k++) {
            int el = (k << 3) + g;
            const float* r = &axy[el << 5];
            int sw = el & 7;
            float4 xa = *(const float4*)&r[(qa ^ sw) << 2];
            float4 ya = *(const float4*)&r[(qb ^ sw) << 2];
            acc[0]  += xa.x * ya.x;  acc[1]  += xa.x * ya.y;
            acc[2]  += xa.x * ya.z;  acc[3]  += xa.x * ya.w;
            acc[4]  += xa.y * ya.x;  acc[5]  += xa.y * ya.y;
            acc[6]  += xa.y * ya.z;  acc[7]  += xa.y * ya.w;
            acc[8]  += xa.z * ya.x;  acc[9]  += xa.z * ya.y;
            acc[10] += xa.z * ya.z;  acc[11] += xa.z * ya.w;
            acc[12] += xa.w * ya.x;  acc[13] += xa.w * ya.y;
            acc[14] += xa.w * ya.z;  acc[15] += xa.w * ya.w;
        }
        __syncthreads();
    }

    // ---- reduce the 8 group copies and write the 16x16 tile ----
#pragma unroll
    for (int m = 0; m < 16; m++) {
        int ci = i0 + (m >> 2);
        int cj = j0 + (m & 3);
        red[((ci << 4) + cj) * 8 + g] = acc[m];
    }
    __syncthreads();
    const float invN = 1.0f / (float)NPIX;
    for (int cell = tid; cell < 256; cell += P2_THREADS) {
        const float* rp = &red[cell * 8];
        float s = ((rp[0] + rp[1]) + (rp[2] + rp[3])) +
                  ((rp[4] + rp[5]) + (rp[6] + rp[7]));
        int ci = cell >> 4, cj = cell & 15;
        out[(size_t)b * (KBINS * KBINS) + (size_t)(klo + ci) * KBINS + (jlo + cj)]
            = s * invN;
    }
}

extern "C" void kernel_launch(void* const* d_in, const int* in_sizes, int n_in,
                              void* d_out, int out_size) {
    const float* x = (const float*)d_in[0];
    const float* y = (const float*)d_in[1];
    float* out = (float*)d_out;

    int B = in_sizes[0] / NPIX;    // 8

    dim3 g1(NSUB, B);
    scatter_kernel<<<g1, P1_THREADS>>>(x, y);

    dim3 g2(NT, NT, B);
    tile_kernel<<<g2, P2_THREADS>>>(out, B);
}

// round 11
// speedup vs baseline: 1.4196x; 1.1946x over previous
#include <cuda_runtime.h>
#include <cuda_bf16.h>
#include <math.h>
#include <stdint.h>

// Soft joint histogram as a bucketed tile-GEMM on tensor cores.
// out[b,k,j] = (1/N) sum_n phi_k(x_n) phi_j(y_n); phi has a 9-bin window.
// Phase 1: scatter (x,y) into per-(b, row-tile, col-tile) buckets (<=4/pixel).
// Phase 2: per-bucket CTA computes its 16x16 tile as out = A(16xE)*B(Ex16)
//          via mma.sync.m16n8k8.tf32 over staged phi fragments in smem.

#define KBINS   256
#define RAD     4
#define WIN     9
#define NEDGE   10
#define NPIX    65536
#define BMAX    8
#define TILE    16
#define NT      16
#define NSUB    16
#define CAP     80          // per (bucket, sub-slot); mean 36, +7.3 sigma
#define CHUNK   (NPIX / NSUB)
#define P1_THREADS 512
#define P2_THREADS 128
#define ENT_MAX (NSUB * CAP)    // 1280
#define RS      36              // staged row stride in words (bank-conflict-free)

__device__ float2 g_buck[BMAX * 256 * NSUB * CAP];
__device__ int    g_cnt [BMAX * 256 * NSUB];

// phi for 9 bins [k0-4, k0+4] around t = x*256. One __expf + one rcp.approx
// via prefix/suffix products of A_m = 1 + E0*R^m (edges form a geometric seq).
__device__ __forceinline__ void compute_phis(float t, int k0, float* __restrict__ phi) {
    const float R = 12.182493960703473f;   // exp(2.5)
    float z0 = (t - (float)(k0 - RAD)) * 2.5f;
    float E = __expf(-z0);

    float A[NEDGE];
    float Ei = E;
#pragma unroll
    for (int m = 0; m < NEDGE; m++) { A[m] = 1.0f + Ei; Ei *= R; }

    float pre[NEDGE], suf[NEDGE];
    pre[0] = A[0];
#pragma unroll
    for (int m = 1; m < NEDGE; m++) pre[m] = pre[m - 1] * A[m];
    suf[NEDGE - 1] = A[NEDGE - 1];
#pragma unroll
    for (int m = NEDGE - 2; m >= 0; m--) suf[m] = suf[m + 1] * A[m];

    float inv;
    asm("rcp.approx.f32 %0, %1;" : "=f"(inv) : "f"(pre[NEDGE - 1]));

    float s[NEDGE];
    s[0] = suf[1] * inv;
#pragma unroll
    for (int m = 1; m < NEDGE - 1; m++) s[m] = pre[m - 1] * suf[m + 1] * inv;
    s[NEDGE - 1] = pre[NEDGE - 2] * inv;

#pragma unroll
    for (int i = 0; i < WIN; i++) phi[i] = s[i] - s[i + 1];
}

__device__ __forceinline__ uint32_t f2tf32(float f) {
    uint32_t u;
    asm("cvt.rna.tf32.f32 %0, %1;" : "=r"(u) : "f"(f));   // RNA: zero-mean error
    return u;
}

// ---------------- Phase 1: scatter pixels into buckets ----------------
__global__ void __launch_bounds__(P1_THREADS)
scatter_kernel(const float* __restrict__ x, const float* __restrict__ y) {
    __shared__ int cnt[256];
    const int s = blockIdx.x;
    const int b = blockIdx.y;
    const int tid = threadIdx.x;

    for (int i = tid; i < 256; i += P1_THREADS) cnt[i] = 0;
    __syncthreads();

    const float* __restrict__ xb = x + b * NPIX;
    const float* __restrict__ yb = y + b * NPIX;
    const int p0 = s * CHUNK;

    for (int p = p0 + tid; p < p0 + CHUNK; p += P1_THREADS) {
        float xv = xb[p];
        float yv = yb[p];
        int kx = (int)(xv * 256.0f);
        int ky = (int)(yv * 256.0f);
        int alo = max(0, (kx - RAD) >> 4), ahi = min(NT - 1, (kx + RAD) >> 4);
        int clo = max(0, (ky - RAD) >> 4), chi = min(NT - 1, (ky + RAD) >> 4);
        for (int a = alo; a <= ahi; a++) {
            for (int c = clo; c <= chi; c++) {
                int lb = a * TILE + c;
                int slot = atomicAdd(&cnt[lb], 1);
                if (slot < CAP) {
                    size_t base = ((size_t)(b * 256 + lb) * NSUB + s) * CAP;
                    g_buck[base + slot] = make_float2(xv, yv);
                }
            }
        }
    }
    __syncthreads();
    for (int i = tid; i < 256; i += P1_THREADS)
        g_cnt[(b * 256 + i) * NSUB + s] = min(cnt[i], CAP);
}

// ---------------- Phase 2: per-bucket 16x16 tile via tf32 MMA ----------------
// Staged row e: st[e*RS + 0..15] = tf32 phix, [16..31] = tf32 phiy.
// bank(word) = (4e + slot) & 31 -> all fragment loads conflict-free.
__global__ void __launch_bounds__(P2_THREADS)
tile_kernel(float* __restrict__ out, int B) {
    __shared__ float2   ent[ENT_MAX];         // 10.25 KB
    __shared__ uint32_t st[128 * RS];         // 18 KB
    __shared__ float    dred[4 * 256];        // 4 KB
    __shared__ int      cnts[NSUB];
    __shared__ int      pre[NSUB + 1];

    const int c = blockIdx.x, a = blockIdx.y, b = blockIdx.z;
    const int tid = threadIdx.x;
    const int bid = b * 256 + a * TILE + c;

    if (tid < NSUB) cnts[tid] = g_cnt[bid * NSUB + tid];
    __syncthreads();
    if (tid == 0) {
        int acc = 0;
#pragma unroll
        for (int s = 0; s < NSUB; s++) { pre[s] = acc; acc += cnts[s]; }
        pre[NSUB] = acc;
    }
    __syncthreads();

    for (int s = 0; s < NSUB; s++) {
        int n = cnts[s];
        const float2* __restrict__ src = &g_buck[((size_t)bid * NSUB + s) * CAP];
        for (int i = tid; i < n; i += P2_THREADS) ent[pre[s] + i] = src[i];
    }
    __syncthreads();

    const int total = pre[NSUB];
    const int w  = tid >> 5;         // warp 0..3
    const int l  = tid & 31;
    const int g  = l >> 2;           // groupID 0..7
    const int tg = l & 3;            // thread-in-group

    const int klo = a * TILE;
    const int jlo = c * TILE;

    float d00 = 0.f, d01 = 0.f, d02 = 0.f, d03 = 0.f;   // n-cols 0..7
    float d10 = 0.f, d11 = 0.f, d12 = 0.f, d13 = 0.f;   // n-cols 8..15

    for (int base = 0; base < total; base += P2_THREADS) {
        // ---- stage 128 entries: tf32 phi rows ----
        {
            uint4* r4 = (uint4*)&st[tid * RS];
#pragma unroll
            for (int q = 0; q < 8; q++) r4[q] = make_uint4(0u, 0u, 0u, 0u);
            int e = base + tid;
            if (e < total) {
                float2 v = ent[e];
                float tx = v.x * 256.0f;
                float ty = v.y * 256.0f;
                int kx = (int)tx, ky = (int)ty;
                float P1[WIN], P2[WIN];
                compute_phis(tx, kx, P1);
                compute_phis(ty, ky, P2);
                int bx = kx - RAD - klo;
                int by = ky - RAD - jlo;
                uint32_t* row = &st[tid * RS];
#pragma unroll
                for (int u = 0; u < WIN; u++) {
                    int sl = bx + u;
                    if ((unsigned)sl < 16u) row[sl] = f2tf32(P1[u]);
                }
#pragma unroll
                for (int u = 0; u < WIN; u++) {
                    int sl = by + u;
                    if ((unsigned)sl < 16u) row[16 + sl] = f2tf32(P2[u]);
                }
            }
        }
        __syncthreads();

        // ---- each warp: 4 chunks of 8 entries, 2 MMA per chunk ----
#pragma unroll
        for (int q = 0; q < 4; q++) {
            const int be = (w * 4 + q) * 8;
            const uint32_t* A0 = &st[(be + tg) * RS];
            const uint32_t* A4 = A0 + 4 * RS;
            uint32_t a0 = A0[g],      a1 = A0[g + 8];
            uint32_t a2 = A4[g],      a3 = A4[g + 8];
            uint32_t b0 = A0[16 + g], b1 = A4[16 + g];
            uint32_t c0 = A0[24 + g], c1 = A4[24 + g];
            asm volatile(
                "mma.sync.aligned.m16n8k8.row.col.f32.tf32.tf32.f32 "
                "{%0,%1,%2,%3}, {%4,%5,%6,%7}, {%8,%9}, {%0,%1,%2,%3};"
                : "+f"(d00), "+f"(d01), "+f"(d02), "+f"(d03)
                : "r"(a0), "r"(a1), "r"(a2), "r"(a3), "r"(b0), "r"(b1));
            asm volatile(
                "mma.sync.aligned.m16n8k8.row.col.f32.tf32.tf32.f32 "
                "{%0,%1,%2,%3}, {%4,%5,%6,%7}, {%8,%9}, {%0,%1,%2,%3};"
                : "+f"(d10), "+f"(d11), "+f"(d12), "+f"(d13)
                : "r"(a0), "r"(a1), "r"(a2), "r"(a3), "r"(c0), "r"(c1));
        }
        __syncthreads();
    }

    // ---- reduce 4 warp copies, write tile ----
    {
        float* dw = &dred[w * 256];
        dw[g * 16 + 2 * tg]           = d00;
        dw[g * 16 + 2 * tg + 1]       = d01;
        dw[(g + 8) * 16 + 2 * tg]     = d02;
        dw[(g + 8) * 16 + 2 * tg + 1] = d03;
        dw[g * 16 + 8 + 2 * tg]           = d10;
        dw[g * 16 + 8 + 2 * tg + 1]       = d11;
        dw[(g + 8) * 16 + 8 + 2 * tg]     = d12;
        dw[(g + 8) * 16 + 8 + 2 * tg + 1] = d13;
    }
    __syncthreads();

    const float invN = 1.0f / (float)NPIX;
    for (int cell = tid; cell < 256; cell += P2_THREADS) {
        float s = dred[cell] + dred[256 + cell] + dred[512 + cell] + dred[768 + cell];
        int ci = cell >> 4, cj = cell & 15;
        out[(size_t)b * (KBINS * KBINS) + (size_t)(klo + ci) * KBINS + (jlo + cj)]
            = s * invN;
    }
}

extern "C" void kernel_launch(void* const* d_in, const int* in_sizes, int n_in,
                              void* d_out, int out_size) {
    const float* x = (const float*)d_in[0];
    const float* y = (const float*)d_in[1];
    float* out = (float*)d_out;

    int B = in_sizes[0] / NPIX;

    dim3 g1(NSUB, B);
    scatter_kernel<<<g1, P1_THREADS>>>(x, y);

    dim3 g2(NT, NT, B);
    tile_kernel<<<g2, P2_THREADS>>>(out, B);
}